// round 2
// baseline (speedup 1.0000x reference)
#include <cuda_runtime.h>
#include <cuda.h>
#include <cstdint>

// ============================================================
// out = x @ (W + s * kron(A,B) * 2)^T
//   x:(128,8192) W:(8192,8192) A:(512,8192) B:(16,1) s:(1,)  all f32
// out[m,i] = (x@W^T)[m,i] + 2*s*B[i%16]*(x@A^T)[m, i/16]
//
// Kernel 1: TF32 mma.sync GEMM, TMA-fed 3-stage pipeline.
//   68 CTAs: 64 compute x@W^T tiles (128 W-rows each), 4 compute x@A^T.
// Kernel 2: rank-1 combine epilogue.
// No tcgen05 (plain sm_103 target): mma.sync.m16n8k8.tf32 + TMA + mbarrier.
// ============================================================

__device__ __forceinline__ uint32_t smem_u32(const void* p) {
    uint32_t a;
    asm("{ .reg .u64 t; cvta.to.shared.u64 t, %1; cvt.u32.u64 %0, t; }" : "=r"(a) : "l"(p));
    return a;
}

#define MBARRIER_INIT(addr, cnt) \
    asm volatile("mbarrier.init.shared.b64 [%0], %1;" :: "r"((uint32_t)(addr)), "r"((uint32_t)(cnt)) : "memory")

#define MBARRIER_EXPECT_TX(addr, bytes) \
    asm volatile("mbarrier.arrive.expect_tx.shared.b64 _, [%0], %1;" :: "r"((uint32_t)(addr)), "r"((uint32_t)(bytes)) : "memory")

#define MBARRIER_ARRIVE(addr) \
    asm volatile("mbarrier.arrive.shared.b64 _, [%0];" :: "r"((uint32_t)(addr)) : "memory")

#define MBARRIER_WAIT_PARITY(mbar, parity) do {                                      \
    uint32_t _m = (uint32_t)(mbar); uint32_t _p = (uint32_t)(parity);                \
    asm volatile(                                                                    \
        "{\n\t.reg .pred P1;\n\t"                                                    \
        "WAIT_LOOP_%=:\n\t"                                                          \
        "mbarrier.try_wait.parity.shared.b64 P1, [%0], %1;\n\t"                      \
        "@P1 bra.uni WAIT_DONE_%=;\n\t"                                              \
        "bra.uni WAIT_LOOP_%=;\n\t"                                                  \
        "WAIT_DONE_%=:\n\t}"                                                         \
        :: "r"(_m), "r"(_p) : "memory");                                             \
} while (0)

#define TMA_LOAD_2D(smem_addr, map, cx, cy, mbar) \
    asm volatile("cp.async.bulk.tensor.2d.shared::cluster.global.tile.mbarrier::complete_tx::bytes " \
                 "[%0], [%1, {%2, %3}], [%4];" \
        :: "r"((uint32_t)(smem_addr)), "l"(map), "r"((int)(cx)), "r"((int)(cy)), "r"((uint32_t)(mbar)) : "memory")

__device__ __forceinline__ float ldsf(uint32_t a) {
    float f;
    asm volatile("ld.shared.f32 %0, [%1];" : "=f"(f) : "r"(a));
    return f;
}
__device__ __forceinline__ uint32_t f2tf(float f) {
    uint32_t u;
    asm("cvt.rna.tf32.f32 %0, %1;" : "=r"(u) : "f"(f));
    return u;
}
__device__ __forceinline__ void mma_tf32(float* d, uint32_t a0, uint32_t a1, uint32_t a2, uint32_t a3,
                                         uint32_t b0, uint32_t b1) {
    asm volatile(
        "mma.sync.aligned.m16n8k8.row.col.f32.tf32.tf32.f32 "
        "{%0,%1,%2,%3}, {%4,%5,%6,%7}, {%8,%9}, {%0,%1,%2,%3};"
        : "+f"(d[0]), "+f"(d[1]), "+f"(d[2]), "+f"(d[3])
        : "r"(a0), "r"(a1), "r"(a2), "r"(a3), "r"(b0), "r"(b1));
}

// ---------------- config ----------------
static constexpr int KC          = 64;            // K per pipeline chunk
static constexpr int NK          = 8192 / KC;     // 128 chunks
static constexpr int STAGES      = 3;
static constexpr int OPD_BYTES   = 128 * KC * 4;  // 32 KB per operand tile
static constexpr int STAGE_BYTES = 2 * OPD_BYTES; // 64 KB (W tile + x tile)
static constexpr int SMEM_HDR    = 1024;
static constexpr int SMEM_BYTES  = SMEM_HDR + STAGES * STAGE_BYTES;  // 197632
static constexpr int OFF_FULL    = 0;    // 3 x 8B
static constexpr int OFF_EMPTY   = 64;   // 3 x 8B

__device__ float g_Y2[128 * 512];   // x @ A^T, [m][arow]

// ---------------- GEMM kernel ----------------
// A-operand of mma = x (M-dim = 128 x-rows), B-operand = W/A rows (N-dim = 128 per CTA).
// 4 consumer warps (warp tile 64x64) + 1 producer warp.
__global__ void __launch_bounds__(160, 1)
lokr_gemm(const __grid_constant__ CUtensorMap w_map,
          const __grid_constant__ CUtensorMap x_map,
          const __grid_constant__ CUtensorMap a_map,
          float* __restrict__ d_out)
{
    extern __shared__ char smem[];
    const uint32_t sb = smem_u32(smem);
    const int tid  = threadIdx.x;
    const int wid  = tid >> 5;
    const int lane = tid & 31;

    const bool isA = (blockIdx.x >= 64);
    const CUtensorMap* wm = isA ? &a_map : &w_map;
    const int row0 = (isA ? (blockIdx.x - 64) : blockIdx.x) * 128;

    if (tid == 0) {
        #pragma unroll
        for (int s = 0; s < STAGES; s++) {
            MBARRIER_INIT(sb + OFF_FULL  + s * 8, 1);
            MBARRIER_INIT(sb + OFF_EMPTY + s * 8, 4);   // one arrive per consumer warp
        }
    }
    __syncthreads();

    if (tid == 128) {
        // ---------------- producer ----------------
        int es = 0, eph = 1;   // init phase 1: first 3 empty-waits pass immediately
        for (int c = 0; c < NK; c++) {
            MBARRIER_WAIT_PARITY(sb + OFF_EMPTY + es * 8, eph);
            uint32_t full = sb + OFF_FULL + es * 8;
            MBARRIER_EXPECT_TX(full, STAGE_BYTES);
            int kx = c * KC;
            uint32_t st = sb + SMEM_HDR + es * STAGE_BYTES;
            TMA_LOAD_2D(st,          wm,     kx,      row0, full);
            TMA_LOAD_2D(st + 16384,  wm,     kx + 32, row0, full);
            TMA_LOAD_2D(st + 32768,  &x_map, kx,      0,    full);
            TMA_LOAD_2D(st + 49152,  &x_map, kx + 32, 0,    full);
            if (++es == STAGES) { es = 0; eph ^= 1; }
        }
    } else if (wid < 4) {
        // ---------------- consumer ----------------
        float acc[4][8][4] = {};
        const int mw = (wid >> 1) * 64;   // x-row base for this warp
        const int nw = (wid & 1) * 64;    // W-row base for this warp
        const int r8 = lane >> 2;         // row-within-8 for both operands
        const uint32_t pb = (uint32_t)(r8 * 128 + (lane & 3) * 4);

        int cs = 0, cph = 0;
        for (int c = 0; c < NK; c++) {
            MBARRIER_WAIT_PARITY(sb + OFF_FULL + cs * 8, cph);

            const uint32_t wbase = sb + SMEM_HDR + cs * STAGE_BYTES + (uint32_t)(nw * 128) + pb;
            const uint32_t xbase = sb + SMEM_HDR + cs * STAGE_BYTES + OPD_BYTES + (uint32_t)(mw * 128) + pb;
            // swizzled per-thread base addresses, one per 16B-unit index
            uint32_t XW[8], XX[8];
            #pragma unroll
            for (int u = 0; u < 8; u++) {
                uint32_t sw = (uint32_t)((u ^ r8) << 4) - (uint32_t)(u << 4);
                XW[u] = wbase + (uint32_t)(u << 4) + sw;
                XX[u] = xbase + (uint32_t)(u << 4) + sw;
            }

            #pragma unroll
            for (int s = 0; s < 8; s++) {
                const int c0 = (2 * s) & 7, c1 = (2 * s + 1) & 7;
                const uint32_t bx = (s >= 4) ? 16384u : 0u;

                // ---- load all fragments (bank-conflict-free under SW128) ----
                float fb0[8], fb1[8];
                #pragma unroll
                for (int j = 0; j < 8; j++) {
                    fb0[j] = ldsf(XW[c0] + bx + 1024u * j);
                    fb1[j] = ldsf(XW[c1] + bx + 1024u * j);
                }
                float fa[4][4];
                #pragma unroll
                for (int i = 0; i < 4; i++) {
                    fa[i][0] = ldsf(XX[c0] + bx + 2048u * i);
                    fa[i][1] = ldsf(XX[c0] + bx + 2048u * i + 1024u);
                    fa[i][2] = ldsf(XX[c1] + bx + 2048u * i);
                    fa[i][3] = ldsf(XX[c1] + bx + 2048u * i + 1024u);
                }
                // ---- round-to-nearest tf32 (unbiased; truncation would fail tol) ----
                uint32_t ub0[8], ub1[8];
                #pragma unroll
                for (int j = 0; j < 8; j++) { ub0[j] = f2tf(fb0[j]); ub1[j] = f2tf(fb1[j]); }
                #pragma unroll
                for (int i = 0; i < 4; i++) {
                    uint32_t a0 = f2tf(fa[i][0]);
                    uint32_t a1 = f2tf(fa[i][1]);
                    uint32_t a2 = f2tf(fa[i][2]);
                    uint32_t a3 = f2tf(fa[i][3]);
                    #pragma unroll
                    for (int j = 0; j < 8; j++)
                        mma_tf32(acc[i][j], a0, a1, a2, a3, ub0[j], ub1[j]);
                }
            }

            __syncwarp();
            if (lane == 0) MBARRIER_ARRIVE(sb + OFF_EMPTY + cs * 8);
            if (++cs == STAGES) { cs = 0; cph ^= 1; }
        }

        // ---------------- epilogue: registers -> gmem ----------------
        float* ob = isA ? g_Y2 : d_out;
        const int stride = isA ? 512 : 8192;
        #pragma unroll
        for (int i = 0; i < 4; i++) {
            #pragma unroll
            for (int j = 0; j < 8; j++) {
                int m = mw + 16 * i + (lane >> 2);
                int n = row0 + nw + 8 * j + 2 * (lane & 3);
                *reinterpret_cast<float2*>(&ob[(size_t)m * stride + n]) =
                    make_float2(acc[i][j][0], acc[i][j][1]);
                *reinterpret_cast<float2*>(&ob[(size_t)(m + 8) * stride + n]) =
                    make_float2(acc[i][j][2], acc[i][j][3]);
            }
        }
    }
}

// ---------------- combine kernel ----------------
// out[m,i] += 2*scalar*B[i%16]*Y2[m, i/16]
__global__ void __launch_bounds__(256)
lokr_combine(const float* __restrict__ lokrB, const float* __restrict__ scalar,
             float* __restrict__ out)
{
    int idx = blockIdx.x * blockDim.x + threadIdx.x;   // float4 index
    int m = idx >> 11;                                  // 2048 float4 per row
    int r = idx & 2047;
    float coef = 2.0f * scalar[0] * g_Y2[m * 512 + (r >> 2)];
    float4 b4 = reinterpret_cast<const float4*>(lokrB)[r & 3];
    float4 o = reinterpret_cast<float4*>(out)[idx];
    o.x += coef * b4.x;
    o.y += coef * b4.y;
    o.z += coef * b4.z;
    o.w += coef * b4.w;
    reinterpret_cast<float4*>(out)[idx] = o;
}

// ---------------- host ----------------
typedef CUresult (*EncodeFn)(CUtensorMap*, CUtensorMapDataType, cuuint32_t, void*,
                             const cuuint64_t*, const cuuint64_t*, const cuuint32_t*,
                             const cuuint32_t*, CUtensorMapInterleave, CUtensorMapSwizzle,
                             CUtensorMapL2promotion, CUtensorMapFloatOOBfill);

static void make_map2d(EncodeFn enc, CUtensorMap* m, const float* base, uint64_t rows) {
    cuuint64_t dims[2]    = { 8192ull, rows };
    cuuint64_t strides[1] = { 8192ull * sizeof(float) };
    cuuint32_t box[2]     = { 32u, 128u };   // 128B-wide box (SW128 atom), 128 rows
    cuuint32_t es[2]      = { 1u, 1u };
    enc(m, CU_TENSOR_MAP_DATA_TYPE_FLOAT32, 2, (void*)base,
        dims, strides, box, es,
        CU_TENSOR_MAP_INTERLEAVE_NONE, CU_TENSOR_MAP_SWIZZLE_128B,
        CU_TENSOR_MAP_L2_PROMOTION_L2_128B, CU_TENSOR_MAP_FLOAT_OOB_FILL_NONE);
}

extern "C" void kernel_launch(void* const* d_in, const int* in_sizes, int n_in,
                              void* d_out, int out_size)
{
    (void)in_sizes; (void)n_in; (void)out_size;
    const float* x  = (const float*)d_in[0];
    const float* W  = (const float*)d_in[1];
    const float* A  = (const float*)d_in[2];
    const float* B  = (const float*)d_in[3];
    const float* sc = (const float*)d_in[4];

    void* fn = nullptr;
    cudaDriverEntryPointQueryResult qr;
    cudaGetDriverEntryPointByVersion("cuTensorMapEncodeTiled", &fn, 12000,
                                     cudaEnableDefault, &qr);
    EncodeFn enc = (EncodeFn)fn;

    CUtensorMap wm, xm, am;
    make_map2d(enc, &wm, W, 8192);
    make_map2d(enc, &xm, x, 128);
    make_map2d(enc, &am, A, 512);

    cudaFuncSetAttribute(lokr_gemm, cudaFuncAttributeMaxDynamicSharedMemorySize, SMEM_BYTES);

    lokr_gemm<<<68, 160, SMEM_BYTES>>>(wm, xm, am, (float*)d_out);
    lokr_combine<<<1024, 256>>>(B, sc, (float*)d_out);
}

// round 3
// speedup vs baseline: 1.6828x; 1.6828x over previous
#include <cuda_runtime.h>
#include <cuda.h>
#include <cstdint>

// ============================================================
// out = x @ (W + s * kron(A,B) * 2)^T
//   x:(128,8192) W:(8192,8192) A:(512,8192) B:(16,1) s:(1,)  all f32
// out[m,i] = (x@W^T)[m,i] + 2*s*B[i%16]*(x@A^T)[m, i/16]
//
// Round 3: fix occupancy. 64 W-rows per CTA -> 136 CTAs (~full chip).
// TF32 mma.sync, TMA-fed 4-stage pipeline, warp tile 64x32 (64 acc regs).
// ============================================================

__device__ __forceinline__ uint32_t smem_u32(const void* p) {
    uint32_t a;
    asm("{ .reg .u64 t; cvta.to.shared.u64 t, %1; cvt.u32.u64 %0, t; }" : "=r"(a) : "l"(p));
    return a;
}

#define MBARRIER_INIT(addr, cnt) \
    asm volatile("mbarrier.init.shared.b64 [%0], %1;" :: "r"((uint32_t)(addr)), "r"((uint32_t)(cnt)) : "memory")

#define MBARRIER_EXPECT_TX(addr, bytes) \
    asm volatile("mbarrier.arrive.expect_tx.shared.b64 _, [%0], %1;" :: "r"((uint32_t)(addr)), "r"((uint32_t)(bytes)) : "memory")

#define MBARRIER_ARRIVE(addr) \
    asm volatile("mbarrier.arrive.shared.b64 _, [%0];" :: "r"((uint32_t)(addr)) : "memory")

#define MBARRIER_WAIT_PARITY(mbar, parity) do {                                      \
    uint32_t _m = (uint32_t)(mbar); uint32_t _p = (uint32_t)(parity);                \
    asm volatile(                                                                    \
        "{\n\t.reg .pred P1;\n\t"                                                    \
        "WAIT_LOOP_%=:\n\t"                                                          \
        "mbarrier.try_wait.parity.shared.b64 P1, [%0], %1;\n\t"                      \
        "@P1 bra.uni WAIT_DONE_%=;\n\t"                                              \
        "bra.uni WAIT_LOOP_%=;\n\t"                                                  \
        "WAIT_DONE_%=:\n\t}"                                                         \
        :: "r"(_m), "r"(_p) : "memory");                                             \
} while (0)

#define TMA_LOAD_2D(smem_addr, map, cx, cy, mbar) \
    asm volatile("cp.async.bulk.tensor.2d.shared::cluster.global.tile.mbarrier::complete_tx::bytes " \
                 "[%0], [%1, {%2, %3}], [%4];" \
        :: "r"((uint32_t)(smem_addr)), "l"(map), "r"((int)(cx)), "r"((int)(cy)), "r"((uint32_t)(mbar)) : "memory")

__device__ __forceinline__ float ldsf(uint32_t a) {
    float f;
    asm volatile("ld.shared.f32 %0, [%1];" : "=f"(f) : "r"(a));
    return f;
}
__device__ __forceinline__ uint32_t f2tf(float f) {
    uint32_t u;
    asm("cvt.rna.tf32.f32 %0, %1;" : "=r"(u) : "f"(f));
    return u;
}
__device__ __forceinline__ void mma_tf32(float* d, uint32_t a0, uint32_t a1, uint32_t a2, uint32_t a3,
                                         uint32_t b0, uint32_t b1) {
    asm volatile(
        "mma.sync.aligned.m16n8k8.row.col.f32.tf32.tf32.f32 "
        "{%0,%1,%2,%3}, {%4,%5,%6,%7}, {%8,%9}, {%0,%1,%2,%3};"
        : "+f"(d[0]), "+f"(d[1]), "+f"(d[2]), "+f"(d[3])
        : "r"(a0), "r"(a1), "r"(a2), "r"(a3), "r"(b0), "r"(b1));
}

// ---------------- config ----------------
static constexpr int M_CTA       = 64;            // W/A rows per CTA
static constexpr int KC          = 64;            // K per pipeline chunk
static constexpr int NK          = 8192 / KC;     // 128 chunks
static constexpr int STAGES      = 4;
static constexpr int W_BOX       = 8192;          // 32 cols x 64 rows x 4B
static constexpr int X_BOX       = 16384;         // 32 cols x 128 rows x 4B
static constexpr int OFF_X       = 2 * W_BOX;     // x operand within stage
static constexpr int STAGE_BYTES = 2 * W_BOX + 2 * X_BOX;  // 48 KB
static constexpr int SMEM_HDR    = 1024;
static constexpr int SMEM_BYTES  = SMEM_HDR + STAGES * STAGE_BYTES;  // 197632
static constexpr int OFF_FULL    = 0;    // 4 x 8B
static constexpr int OFF_EMPTY   = 64;   // 4 x 8B

__device__ float g_Y2[128 * 512];   // x @ A^T, [m][arow]

// ---------------- GEMM kernel ----------------
// mma A-operand = x (M=128 rows, 2 warps x 64), B-operand = W rows (N=64 per CTA, 2 warps x 32).
__global__ void __launch_bounds__(160, 1)
lokr_gemm(const __grid_constant__ CUtensorMap w_map,
          const __grid_constant__ CUtensorMap x_map,
          const __grid_constant__ CUtensorMap a_map,
          float* __restrict__ d_out)
{
    extern __shared__ char smem[];
    const uint32_t sb = smem_u32(smem);
    const int tid  = threadIdx.x;
    const int wid  = tid >> 5;
    const int lane = tid & 31;

    const bool isA = (blockIdx.x >= 128);
    const CUtensorMap* wm = isA ? &a_map : &w_map;
    const int row0 = (isA ? (blockIdx.x - 128) : blockIdx.x) * M_CTA;

    if (tid == 0) {
        #pragma unroll
        for (int s = 0; s < STAGES; s++) {
            MBARRIER_INIT(sb + OFF_FULL  + s * 8, 1);
            MBARRIER_INIT(sb + OFF_EMPTY + s * 8, 4);   // one arrive per consumer warp
        }
    }
    __syncthreads();

    if (tid == 128) {
        // ---------------- producer ----------------
        int es = 0, eph = 1;   // phase 1: first STAGES empty-waits pass immediately
        for (int c = 0; c < NK; c++) {
            MBARRIER_WAIT_PARITY(sb + OFF_EMPTY + es * 8, eph);
            uint32_t full = sb + OFF_FULL + es * 8;
            MBARRIER_EXPECT_TX(full, STAGE_BYTES);
            int kx = c * KC;
            uint32_t st = sb + SMEM_HDR + es * STAGE_BYTES;
            TMA_LOAD_2D(st,                 wm,     kx,      row0, full);
            TMA_LOAD_2D(st + W_BOX,         wm,     kx + 32, row0, full);
            TMA_LOAD_2D(st + OFF_X,         &x_map, kx,      0,    full);
            TMA_LOAD_2D(st + OFF_X + X_BOX, &x_map, kx + 32, 0,    full);
            if (++es == STAGES) { es = 0; eph ^= 1; }
        }
    } else if (wid < 4) {
        // ---------------- consumer ----------------
        float acc[4][4][4] = {};              // [i: x 16-row][j: W 8-col][frag]
        const int mw = (wid >> 1) * 64;       // x-row base
        const int nw = (wid & 1) * 32;        // W-row base within CTA tile
        const int r8 = lane >> 2;             // row-in-8 (same for both operands)
        // loop-invariant swizzle offsets: 16B-unit u XORed with row%8
        uint32_t swz[8];
        #pragma unroll
        for (int u = 0; u < 8; u++) swz[u] = (uint32_t)((u ^ r8) << 4);
        const uint32_t pbW = (uint32_t)((nw + r8) * 128 + (lane & 3) * 4);
        const uint32_t pbX = (uint32_t)((mw + r8) * 128 + (lane & 3) * 4);

        int cs = 0, cph = 0;
        for (int c = 0; c < NK; c++) {
            MBARRIER_WAIT_PARITY(sb + OFF_FULL + cs * 8, cph);

            const uint32_t stg   = sb + SMEM_HDR + (uint32_t)cs * STAGE_BYTES;
            const uint32_t wbase = stg + pbW;
            const uint32_t xbase = stg + OFF_X + pbX;

            #pragma unroll
            for (int s = 0; s < 8; s++) {
                const uint32_t c0 = swz[2 * (s & 3)], c1 = swz[2 * (s & 3) + 1];
                const uint32_t bxW = (s >= 4) ? (uint32_t)W_BOX : 0u;
                const uint32_t bxX = (s >= 4) ? (uint32_t)X_BOX : 0u;
                const uint32_t wb = wbase + bxW;
                const uint32_t xb = xbase + bxX;

                // B fragments (W): 8 LDS, conflict-free under SW128
                float fb0[4], fb1[4];
                #pragma unroll
                for (int j = 0; j < 4; j++) {
                    fb0[j] = ldsf(wb + c0 + 1024u * j);
                    fb1[j] = ldsf(wb + c1 + 1024u * j);
                }
                // A fragments (x): 16 LDS
                float fa[4][4];
                #pragma unroll
                for (int i = 0; i < 4; i++) {
                    fa[i][0] = ldsf(xb + c0 + 2048u * i);
                    fa[i][1] = ldsf(xb + c0 + 2048u * i + 1024u);
                    fa[i][2] = ldsf(xb + c1 + 2048u * i);
                    fa[i][3] = ldsf(xb + c1 + 2048u * i + 1024u);
                }
                // round-to-nearest tf32 (truncation would bias K=8192 sum past tol)
                uint32_t ub0[4], ub1[4];
                #pragma unroll
                for (int j = 0; j < 4; j++) { ub0[j] = f2tf(fb0[j]); ub1[j] = f2tf(fb1[j]); }
                #pragma unroll
                for (int i = 0; i < 4; i++) {
                    uint32_t a0 = f2tf(fa[i][0]);
                    uint32_t a1 = f2tf(fa[i][1]);
                    uint32_t a2 = f2tf(fa[i][2]);
                    uint32_t a3 = f2tf(fa[i][3]);
                    #pragma unroll
                    for (int j = 0; j < 4; j++)
                        mma_tf32(acc[i][j], a0, a1, a2, a3, ub0[j], ub1[j]);
                }
            }

            __syncwarp();
            if (lane == 0) MBARRIER_ARRIVE(sb + OFF_EMPTY + cs * 8);
            if (++cs == STAGES) { cs = 0; cph ^= 1; }
        }

        // ---------------- epilogue ----------------
        float* ob = isA ? g_Y2 : d_out;
        const int stride = isA ? 512 : 8192;
        #pragma unroll
        for (int i = 0; i < 4; i++) {
            #pragma unroll
            for (int j = 0; j < 4; j++) {
                int m = mw + 16 * i + r8;
                int n = row0 + nw + 8 * j + 2 * (lane & 3);
                *reinterpret_cast<float2*>(&ob[(size_t)m * stride + n]) =
                    make_float2(acc[i][j][0], acc[i][j][1]);
                *reinterpret_cast<float2*>(&ob[(size_t)(m + 8) * stride + n]) =
                    make_float2(acc[i][j][2], acc[i][j][3]);
            }
        }
    }
}

// ---------------- combine kernel ----------------
// out[m,i] += 2*scalar*B[i%16]*Y2[m, i/16]
__global__ void __launch_bounds__(256)
lokr_combine(const float* __restrict__ lokrB, const float* __restrict__ scalar,
             float* __restrict__ out)
{
    int idx = blockIdx.x * blockDim.x + threadIdx.x;   // float4 index
    int m = idx >> 11;                                  // 2048 float4 per row
    int r = idx & 2047;
    float coef = 2.0f * scalar[0] * g_Y2[m * 512 + (r >> 2)];
    float4 b4 = reinterpret_cast<const float4*>(lokrB)[r & 3];
    float4 o = reinterpret_cast<float4*>(out)[idx];
    o.x += coef * b4.x;
    o.y += coef * b4.y;
    o.z += coef * b4.z;
    o.w += coef * b4.w;
    reinterpret_cast<float4*>(out)[idx] = o;
}

// ---------------- host ----------------
typedef CUresult (*EncodeFn)(CUtensorMap*, CUtensorMapDataType, cuuint32_t, void*,
                             const cuuint64_t*, const cuuint64_t*, const cuuint32_t*,
                             const cuuint32_t*, CUtensorMapInterleave, CUtensorMapSwizzle,
                             CUtensorMapL2promotion, CUtensorMapFloatOOBfill);

static void make_map2d(EncodeFn enc, CUtensorMap* m, const float* base, uint64_t rows,
                       uint32_t box_h) {
    cuuint64_t dims[2]    = { 8192ull, rows };
    cuuint64_t strides[1] = { 8192ull * sizeof(float) };
    cuuint32_t box[2]     = { 32u, box_h };   // 128B-wide box (SW128 atom)
    cuuint32_t es[2]      = { 1u, 1u };
    enc(m, CU_TENSOR_MAP_DATA_TYPE_FLOAT32, 2, (void*)base,
        dims, strides, box, es,
        CU_TENSOR_MAP_INTERLEAVE_NONE, CU_TENSOR_MAP_SWIZZLE_128B,
        CU_TENSOR_MAP_L2_PROMOTION_L2_128B, CU_TENSOR_MAP_FLOAT_OOB_FILL_NONE);
}

extern "C" void kernel_launch(void* const* d_in, const int* in_sizes, int n_in,
                              void* d_out, int out_size)
{
    (void)in_sizes; (void)n_in; (void)out_size;
    const float* x  = (const float*)d_in[0];
    const float* W  = (const float*)d_in[1];
    const float* A  = (const float*)d_in[2];
    const float* B  = (const float*)d_in[3];
    const float* sc = (const float*)d_in[4];

    void* fn = nullptr;
    cudaDriverEntryPointQueryResult qr;
    cudaGetDriverEntryPointByVersion("cuTensorMapEncodeTiled", &fn, 12000,
                                     cudaEnableDefault, &qr);
    EncodeFn enc = (EncodeFn)fn;

    CUtensorMap wm, xm, am;
    make_map2d(enc, &wm, W, 8192, 64);
    make_map2d(enc, &xm, x, 128, 128);
    make_map2d(enc, &am, A, 512, 64);

    cudaFuncSetAttribute(lokr_gemm, cudaFuncAttributeMaxDynamicSharedMemorySize, SMEM_BYTES);

    lokr_gemm<<<136, 160, SMEM_BYTES>>>(wm, xm, am, (float*)d_out);
    lokr_combine<<<1024, 256>>>(B, sc, (float*)d_out);
}

// round 4
// speedup vs baseline: 1.7412x; 1.0347x over previous
#include <cuda_runtime.h>
#include <cuda.h>
#include <cstdint>

// ============================================================
// out = x @ (W + s * kron(A,B) * 2)^T
// out[m,i] = (x@W^T)[m,i] + 2*s*B[i%16]*(x@A^T)[m, i/16]
//
// Round 4: grid k-split. 136 CTAs = (64 W-tiles + 4 A-tiles) x 2 k-halves.
//   M_CTA=128 rows, each CTA reads half of x -> L2 traffic 816->560 MB.
//   8 consumer warps (2/SMSP) for latency hiding, warp tile 64x32.
//   kh=0 -> d_out, kh=1 -> g_P1; combine kernel sums + rank-1 term.
// ============================================================

__device__ __forceinline__ uint32_t smem_u32(const void* p) {
    uint32_t a;
    asm("{ .reg .u64 t; cvta.to.shared.u64 t, %1; cvt.u32.u64 %0, t; }" : "=r"(a) : "l"(p));
    return a;
}

#define MBARRIER_INIT(addr, cnt) \
    asm volatile("mbarrier.init.shared.b64 [%0], %1;" :: "r"((uint32_t)(addr)), "r"((uint32_t)(cnt)) : "memory")

#define MBARRIER_EXPECT_TX(addr, bytes) \
    asm volatile("mbarrier.arrive.expect_tx.shared.b64 _, [%0], %1;" :: "r"((uint32_t)(addr)), "r"((uint32_t)(bytes)) : "memory")

#define MBARRIER_ARRIVE(addr) \
    asm volatile("mbarrier.arrive.shared.b64 _, [%0];" :: "r"((uint32_t)(addr)) : "memory")

#define MBARRIER_WAIT_PARITY(mbar, parity) do {                                      \
    uint32_t _m = (uint32_t)(mbar); uint32_t _p = (uint32_t)(parity);                \
    asm volatile(                                                                    \
        "{\n\t.reg .pred P1;\n\t"                                                    \
        "WAIT_LOOP_%=:\n\t"                                                          \
        "mbarrier.try_wait.parity.shared.b64 P1, [%0], %1;\n\t"                      \
        "@P1 bra.uni WAIT_DONE_%=;\n\t"                                              \
        "bra.uni WAIT_LOOP_%=;\n\t"                                                  \
        "WAIT_DONE_%=:\n\t}"                                                         \
        :: "r"(_m), "r"(_p) : "memory");                                             \
} while (0)

#define TMA_LOAD_2D(smem_addr, map, cx, cy, mbar) \
    asm volatile("cp.async.bulk.tensor.2d.shared::cluster.global.tile.mbarrier::complete_tx::bytes " \
                 "[%0], [%1, {%2, %3}], [%4];" \
        :: "r"((uint32_t)(smem_addr)), "l"(map), "r"((int)(cx)), "r"((int)(cy)), "r"((uint32_t)(mbar)) : "memory")

__device__ __forceinline__ float ldsf(uint32_t a) {
    float f;
    asm volatile("ld.shared.f32 %0, [%1];" : "=f"(f) : "r"(a));
    return f;
}
__device__ __forceinline__ uint32_t f2tf(float f) {
    uint32_t u;
    asm("cvt.rna.tf32.f32 %0, %1;" : "=r"(u) : "f"(f));
    return u;
}
__device__ __forceinline__ void mma_tf32(float* d, uint32_t a0, uint32_t a1, uint32_t a2, uint32_t a3,
                                         uint32_t b0, uint32_t b1) {
    asm volatile(
        "mma.sync.aligned.m16n8k8.row.col.f32.tf32.tf32.f32 "
        "{%0,%1,%2,%3}, {%4,%5,%6,%7}, {%8,%9}, {%0,%1,%2,%3};"
        : "+f"(d[0]), "+f"(d[1]), "+f"(d[2]), "+f"(d[3])
        : "r"(a0), "r"(a1), "r"(a2), "r"(a3), "r"(b0), "r"(b1));
}

// ---------------- config ----------------
static constexpr int KC          = 64;            // K per pipeline chunk
static constexpr int KHALF       = 4096;          // K per CTA (grid k-split)
static constexpr int NK          = KHALF / KC;    // 64 chunks per CTA
static constexpr int STAGES      = 3;
static constexpr int BOX_BYTES   = 16384;         // 32 cols x 128 rows x 4B
static constexpr int OFF_X       = 2 * BOX_BYTES; // x operand within stage
static constexpr int STAGE_BYTES = 4 * BOX_BYTES; // 64 KB (W 32K + x 32K)
static constexpr int SMEM_HDR    = 1024;
static constexpr int SMEM_BYTES  = SMEM_HDR + STAGES * STAGE_BYTES;  // 197632
static constexpr int OFF_FULL    = 0;    // 3 x 8B
static constexpr int OFF_EMPTY   = 64;   // 3 x 8B

__device__ float g_P1[128 * 8192];    // k-half-1 partial of x@W^T
__device__ float g_Y2[2][128 * 512];  // k-half partials of x@A^T, [m][arow]

// ---------------- GEMM kernel ----------------
// bid 0..127: W tile (bid>>1), k-half (bid&1).  bid 128..135: A tile ((bid-128)>>1), k-half (bid&1).
// mma A-operand = x (128 rows), B-operand = W/A rows (128 per CTA).
// 8 consumer warps: wn = wid>>1 (4 x 32 W-rows), wm = wid&1 (2 x 64 x-rows). 1 producer warp.
__global__ void __launch_bounds__(288, 1)
lokr_gemm(const __grid_constant__ CUtensorMap w_map,
          const __grid_constant__ CUtensorMap x_map,
          const __grid_constant__ CUtensorMap a_map,
          float* __restrict__ d_out)
{
    extern __shared__ char smem[];
    const uint32_t sb = smem_u32(smem);
    const int tid  = threadIdx.x;
    const int wid  = tid >> 5;
    const int lane = tid & 31;

    const bool isA = (blockIdx.x >= 128);
    const int  kh  = blockIdx.x & 1;
    const int  k0  = kh * KHALF;
    const CUtensorMap* wm_map = isA ? &a_map : &w_map;
    const int row0 = (isA ? ((blockIdx.x - 128) >> 1) : (blockIdx.x >> 1)) * 128;

    if (tid == 0) {
        #pragma unroll
        for (int s = 0; s < STAGES; s++) {
            MBARRIER_INIT(sb + OFF_FULL  + s * 8, 1);
            MBARRIER_INIT(sb + OFF_EMPTY + s * 8, 8);   // one arrive per consumer warp
        }
    }
    __syncthreads();

    if (tid == 256) {
        // ---------------- producer ----------------
        int es = 0, eph = 1;   // phase 1: first STAGES empty-waits pass immediately
        for (int c = 0; c < NK; c++) {
            MBARRIER_WAIT_PARITY(sb + OFF_EMPTY + es * 8, eph);
            uint32_t full = sb + OFF_FULL + es * 8;
            MBARRIER_EXPECT_TX(full, STAGE_BYTES);
            int kx = k0 + c * KC;
            uint32_t st = sb + SMEM_HDR + es * STAGE_BYTES;
            TMA_LOAD_2D(st,                     wm_map, kx,      row0, full);
            TMA_LOAD_2D(st + BOX_BYTES,         wm_map, kx + 32, row0, full);
            TMA_LOAD_2D(st + OFF_X,             &x_map, kx,      0,    full);
            TMA_LOAD_2D(st + OFF_X + BOX_BYTES, &x_map, kx + 32, 0,    full);
            if (++es == STAGES) { es = 0; eph ^= 1; }
        }
    } else if (wid < 8) {
        // ---------------- consumer ----------------
        float acc[4][4][4] = {};              // [i: x 16-row][j: W 8-col][frag]
        const int mw = (wid & 1) * 64;        // x-row base (2 warps)
        const int nw = (wid >> 1) * 32;       // W-row base (4 warps)
        const int r8 = lane >> 2;             // row-in-8 (both operands)
        uint32_t swz[8];
        #pragma unroll
        for (int u = 0; u < 8; u++) swz[u] = (uint32_t)((u ^ r8) << 4);
        const uint32_t pbW = (uint32_t)((nw + r8) * 128 + (lane & 3) * 4);
        const uint32_t pbX = (uint32_t)((mw + r8) * 128 + (lane & 3) * 4);

        int cs = 0, cph = 0;
        for (int c = 0; c < NK; c++) {
            MBARRIER_WAIT_PARITY(sb + OFF_FULL + cs * 8, cph);

            const uint32_t stg   = sb + SMEM_HDR + (uint32_t)cs * STAGE_BYTES;
            const uint32_t wbase = stg + pbW;
            const uint32_t xbase = stg + OFF_X + pbX;

            #pragma unroll
            for (int s = 0; s < 8; s++) {
                const uint32_t c0 = swz[2 * (s & 3)], c1 = swz[2 * (s & 3) + 1];
                const uint32_t bx = (s >= 4) ? (uint32_t)BOX_BYTES : 0u;
                const uint32_t wb = wbase + bx;
                const uint32_t xb = xbase + bx;

                float fb0[4], fb1[4];
                #pragma unroll
                for (int j = 0; j < 4; j++) {
                    fb0[j] = ldsf(wb + c0 + 1024u * j);
                    fb1[j] = ldsf(wb + c1 + 1024u * j);
                }
                float fa[4][4];
                #pragma unroll
                for (int i = 0; i < 4; i++) {
                    fa[i][0] = ldsf(xb + c0 + 2048u * i);
                    fa[i][1] = ldsf(xb + c0 + 2048u * i + 1024u);
                    fa[i][2] = ldsf(xb + c1 + 2048u * i);
                    fa[i][3] = ldsf(xb + c1 + 2048u * i + 1024u);
                }
                uint32_t ub0[4], ub1[4];
                #pragma unroll
                for (int j = 0; j < 4; j++) { ub0[j] = f2tf(fb0[j]); ub1[j] = f2tf(fb1[j]); }
                #pragma unroll
                for (int i = 0; i < 4; i++) {
                    uint32_t a0 = f2tf(fa[i][0]);
                    uint32_t a1 = f2tf(fa[i][1]);
                    uint32_t a2 = f2tf(fa[i][2]);
                    uint32_t a3 = f2tf(fa[i][3]);
                    #pragma unroll
                    for (int j = 0; j < 4; j++)
                        mma_tf32(acc[i][j], a0, a1, a2, a3, ub0[j], ub1[j]);
                }
            }

            __syncwarp();
            if (lane == 0) MBARRIER_ARRIVE(sb + OFF_EMPTY + cs * 8);
            if (++cs == STAGES) { cs = 0; cph ^= 1; }
        }

        // ---------------- epilogue: partial -> its buffer ----------------
        float* ob;
        int stride;
        if (isA) { ob = g_Y2[kh]; stride = 512; }
        else     { ob = kh ? g_P1 : d_out; stride = 8192; }
        #pragma unroll
        for (int i = 0; i < 4; i++) {
            #pragma unroll
            for (int j = 0; j < 4; j++) {
                int m = mw + 16 * i + r8;
                int n = row0 + nw + 8 * j + 2 * (lane & 3);
                *reinterpret_cast<float2*>(&ob[(size_t)m * stride + n]) =
                    make_float2(acc[i][j][0], acc[i][j][1]);
                *reinterpret_cast<float2*>(&ob[(size_t)(m + 8) * stride + n]) =
                    make_float2(acc[i][j][2], acc[i][j][3]);
            }
        }
    }
}

// ---------------- combine kernel ----------------
// out[m, 16q+e] = out + P1 + 2*s*B[e]*(Y2a[m,q]+Y2b[m,q]);  one thread per (m,q) group of 16.
__global__ void __launch_bounds__(256)
lokr_combine(const float* __restrict__ lokrB, const float* __restrict__ scalar,
             float* __restrict__ out)
{
    int g = blockIdx.x * blockDim.x + threadIdx.x;   // 0 .. 128*512-1
    int m = g >> 9;
    int q = g & 511;
    float coef = 2.0f * scalar[0] * (g_Y2[0][m * 512 + q] + g_Y2[1][m * 512 + q]);

    const float4* Bv = reinterpret_cast<const float4*>(lokrB);
    size_t base = ((size_t)m * 8192 + (size_t)q * 16) >> 2;   // float4 index
    float4* o4 = reinterpret_cast<float4*>(out);
    const float4* p4 = reinterpret_cast<const float4*>(g_P1);

    #pragma unroll
    for (int t = 0; t < 4; t++) {
        float4 o = o4[base + t];
        float4 p = p4[base + t];
        float4 b = Bv[t];
        o.x += p.x + coef * b.x;
        o.y += p.y + coef * b.y;
        o.z += p.z + coef * b.z;
        o.w += p.w + coef * b.w;
        o4[base + t] = o;
    }
}

// ---------------- host ----------------
typedef CUresult (*EncodeFn)(CUtensorMap*, CUtensorMapDataType, cuuint32_t, void*,
                             const cuuint64_t*, const cuuint64_t*, const cuuint32_t*,
                             const cuuint32_t*, CUtensorMapInterleave, CUtensorMapSwizzle,
                             CUtensorMapL2promotion, CUtensorMapFloatOOBfill);

static void make_map2d(EncodeFn enc, CUtensorMap* m, const float* base, uint64_t rows) {
    cuuint64_t dims[2]    = { 8192ull, rows };
    cuuint64_t strides[1] = { 8192ull * sizeof(float) };
    cuuint32_t box[2]     = { 32u, 128u };   // 128B-wide box (SW128 atom), 128 rows
    cuuint32_t es[2]      = { 1u, 1u };
    enc(m, CU_TENSOR_MAP_DATA_TYPE_FLOAT32, 2, (void*)base,
        dims, strides, box, es,
        CU_TENSOR_MAP_INTERLEAVE_NONE, CU_TENSOR_MAP_SWIZZLE_128B,
        CU_TENSOR_MAP_L2_PROMOTION_L2_128B, CU_TENSOR_MAP_FLOAT_OOB_FILL_NONE);
}

extern "C" void kernel_launch(void* const* d_in, const int* in_sizes, int n_in,
                              void* d_out, int out_size)
{
    (void)in_sizes; (void)n_in; (void)out_size;
    const float* x  = (const float*)d_in[0];
    const float* W  = (const float*)d_in[1];
    const float* A  = (const float*)d_in[2];
    const float* B  = (const float*)d_in[3];
    const float* sc = (const float*)d_in[4];

    void* fn = nullptr;
    cudaDriverEntryPointQueryResult qr;
    cudaGetDriverEntryPointByVersion("cuTensorMapEncodeTiled", &fn, 12000,
                                     cudaEnableDefault, &qr);
    EncodeFn enc = (EncodeFn)fn;

    CUtensorMap wm, xm, am;
    make_map2d(enc, &wm, W, 8192);
    make_map2d(enc, &xm, x, 128);
    make_map2d(enc, &am, A, 512);

    cudaFuncSetAttribute(lokr_gemm, cudaFuncAttributeMaxDynamicSharedMemorySize, SMEM_BYTES);

    lokr_gemm<<<136, 288, SMEM_BYTES>>>(wm, xm, am, (float*)d_out);
    lokr_combine<<<256, 256>>>(B, sc, (float*)d_out);
}

// round 5
// speedup vs baseline: 1.7678x; 1.0153x over previous
#include <cuda_runtime.h>
#include <cuda.h>
#include <cstdint>

// ============================================================
// out = x @ (W + s * kron(A,B) * 2)^T
// out[m,i] = (x@W^T)[m,i] + 2*s*B[i%16]*(x@A^T)[m, i/16]
//
// Round 5: discriminate crossbar vs legacy-HMMA binder.
//  - 136 CTAs = (32 W-tiles + 2 A-tiles) x 4 k-quarters, M_CTA=256 rows.
//  - warp tile 64x64 (128 acc regs), 8 consumer warps + 1 producer.
//  - x pre-packed into fragment order + pre-rounded to tf32 (prep kernel),
//    loaded via 1D cp.async.bulk -> A-fragment = one LDS.128, zero CVT.
//  - W via TMA SW128, B-fragments LDS.32 + RN cvt (needed for bias).
//  - 4-way k partials: kq0 -> d_out, kq1..3 -> g_P; fused combine.
// ============================================================

__device__ __forceinline__ uint32_t smem_u32(const void* p) {
    uint32_t a;
    asm("{ .reg .u64 t; cvta.to.shared.u64 t, %1; cvt.u32.u64 %0, t; }" : "=r"(a) : "l"(p));
    return a;
}

#define MBARRIER_INIT(addr, cnt) \
    asm volatile("mbarrier.init.shared.b64 [%0], %1;" :: "r"((uint32_t)(addr)), "r"((uint32_t)(cnt)) : "memory")

#define MBARRIER_EXPECT_TX(addr, bytes) \
    asm volatile("mbarrier.arrive.expect_tx.shared.b64 _, [%0], %1;" :: "r"((uint32_t)(addr)), "r"((uint32_t)(bytes)) : "memory")

#define MBARRIER_ARRIVE(addr) \
    asm volatile("mbarrier.arrive.shared.b64 _, [%0];" :: "r"((uint32_t)(addr)) : "memory")

#define MBARRIER_WAIT_PARITY(mbar, parity) do {                                      \
    uint32_t _m = (uint32_t)(mbar); uint32_t _p = (uint32_t)(parity);                \
    asm volatile(                                                                    \
        "{\n\t.reg .pred P1;\n\t"                                                    \
        "WAIT_LOOP_%=:\n\t"                                                          \
        "mbarrier.try_wait.parity.shared.b64 P1, [%0], %1;\n\t"                      \
        "@P1 bra.uni WAIT_DONE_%=;\n\t"                                              \
        "bra.uni WAIT_LOOP_%=;\n\t"                                                  \
        "WAIT_DONE_%=:\n\t}"                                                         \
        :: "r"(_m), "r"(_p) : "memory");                                             \
} while (0)

#define TMA_LOAD_2D(smem_addr, map, cx, cy, mbar) \
    asm volatile("cp.async.bulk.tensor.2d.shared::cluster.global.tile.mbarrier::complete_tx::bytes " \
                 "[%0], [%1, {%2, %3}], [%4];" \
        :: "r"((uint32_t)(smem_addr)), "l"(map), "r"((int)(cx)), "r"((int)(cy)), "r"((uint32_t)(mbar)) : "memory")

#define BULK_LOAD(smem_addr, gptr, bytes, mbar) \
    asm volatile("cp.async.bulk.shared::cluster.global.mbarrier::complete_tx::bytes " \
                 "[%0], [%1], %2, [%3];" \
        :: "r"((uint32_t)(smem_addr)), "l"(gptr), "r"((uint32_t)(bytes)), "r"((uint32_t)(mbar)) : "memory")

__device__ __forceinline__ float ldsf(uint32_t a) {
    float f;
    asm volatile("ld.shared.f32 %0, [%1];" : "=f"(f) : "r"(a));
    return f;
}
__device__ __forceinline__ void lds128(uint32_t a, uint32_t& r0, uint32_t& r1, uint32_t& r2, uint32_t& r3) {
    asm volatile("ld.shared.v4.b32 {%0,%1,%2,%3}, [%4];"
                 : "=r"(r0), "=r"(r1), "=r"(r2), "=r"(r3) : "r"(a));
}
__device__ __forceinline__ uint32_t f2tf(float f) {
    uint32_t u;
    asm("cvt.rna.tf32.f32 %0, %1;" : "=r"(u) : "f"(f));
    return u;
}
__device__ __forceinline__ void mma_tf32(float* d, uint32_t a0, uint32_t a1, uint32_t a2, uint32_t a3,
                                         uint32_t b0, uint32_t b1) {
    asm volatile(
        "mma.sync.aligned.m16n8k8.row.col.f32.tf32.tf32.f32 "
        "{%0,%1,%2,%3}, {%4,%5,%6,%7}, {%8,%9}, {%0,%1,%2,%3};"
        : "+f"(d[0]), "+f"(d[1]), "+f"(d[2]), "+f"(d[3])
        : "r"(a0), "r"(a1), "r"(a2), "r"(a3), "r"(b0), "r"(b1));
}

// ---------------- config ----------------
static constexpr int KQ          = 2048;          // K per CTA (quarter)
static constexpr int KC          = 32;            // K per pipeline chunk
static constexpr int NK          = KQ / KC;       // 64 chunks
static constexpr int STAGES      = 4;
static constexpr int W_STAGE     = 32768;         // 32 cols x 256 rows x 4B
static constexpr int X_STAGE     = 16384;         // packed x: 8 mb x 4 s x 32 t x 16B
static constexpr int STAGE_BYTES = W_STAGE + X_STAGE;  // 48 KB
static constexpr int SMEM_HDR    = 1024;
static constexpr int SMEM_BYTES  = SMEM_HDR + STAGES * STAGE_BYTES;  // 197632
static constexpr int OFF_FULL    = 0;
static constexpr int OFF_EMPTY   = 64;

__device__ float g_xpack[128 * 8192];      // x in tf32-rounded fragment order
__device__ float g_P[3][128 * 8192];       // k-quarter partials 1..3 of x@W^T
__device__ float g_Y2[4][128 * 512];       // k-quarter partials of x@A^T

// ---------------- prep: pack x into fragment order + RN-tf32 ----------------
// packed[kc][mb][s][lane] = float4 {x[m][k], x[m+8][k], x[m][k+4], x[m+8][k+4]}
//   m = mb*16 + lane/4, k = kc*32 + s*8 + lane%4
__global__ void __launch_bounds__(256)
prep_x(const float* __restrict__ x)
{
    int t    = blockIdx.x * blockDim.x + threadIdx.x;   // 0..262143 float4 id
    int lane = t & 31;
    int s    = (t >> 5) & 3;
    int mb   = (t >> 7) & 7;
    int kc   = t >> 10;
    int m = mb * 16 + (lane >> 2);
    int k = kc * 32 + s * 8 + (lane & 3);
    uint4 v;
    v.x = f2tf(x[(size_t)m * 8192 + k]);
    v.y = f2tf(x[(size_t)(m + 8) * 8192 + k]);
    v.z = f2tf(x[(size_t)m * 8192 + k + 4]);
    v.w = f2tf(x[(size_t)(m + 8) * 8192 + k + 4]);
    reinterpret_cast<uint4*>(g_xpack)[t] = v;
}

// ---------------- GEMM kernel ----------------
// bid<128: W tile (bid>>2)*256 rows, kq=bid&3.  bid>=128: A tile ((bid-128)>>2)*256, kq=(bid-128)&3.
// 8 consumer warps: wm = wid&1 (x-row half), nw = (wid>>1)*64 (W-row slice). 1 producer warp.
__global__ void __launch_bounds__(288, 1)
lokr_gemm(const __grid_constant__ CUtensorMap w_map,
          const __grid_constant__ CUtensorMap a_map,
          float* __restrict__ d_out)
{
    extern __shared__ char smem[];
    const uint32_t sb = smem_u32(smem);
    const int tid  = threadIdx.x;
    const int wid  = tid >> 5;
    const int lane = tid & 31;

    const bool isA = (blockIdx.x >= 128);
    const int  b   = isA ? (blockIdx.x - 128) : blockIdx.x;
    const int  kq  = b & 3;
    const int  row0 = (b >> 2) * 256;
    const CUtensorMap* wm_map = isA ? &a_map : &w_map;

    if (tid == 0) {
        #pragma unroll
        for (int s = 0; s < STAGES; s++) {
            MBARRIER_INIT(sb + OFF_FULL  + s * 8, 1);
            MBARRIER_INIT(sb + OFF_EMPTY + s * 8, 8);
        }
    }
    __syncthreads();

    if (tid == 256) {
        // ---------------- producer ----------------
        const float* xp = g_xpack + (size_t)kq * (64 * 4096);
        int es = 0, eph = 1;
        for (int c = 0; c < NK; c++) {
            MBARRIER_WAIT_PARITY(sb + OFF_EMPTY + es * 8, eph);
            uint32_t full = sb + OFF_FULL + es * 8;
            MBARRIER_EXPECT_TX(full, STAGE_BYTES);
            uint32_t st = sb + SMEM_HDR + es * STAGE_BYTES;
            TMA_LOAD_2D(st, wm_map, kq * KQ + c * KC, row0, full);
            BULK_LOAD(st + W_STAGE, xp + (size_t)c * 4096, X_STAGE, full);
            if (++es == STAGES) { es = 0; eph ^= 1; }
        }
    } else if (wid < 8) {
        // ---------------- consumer ----------------
        float acc[4][8][4] = {};             // [i: x m16-block][j: W n8-block][frag]
        const int wm = wid & 1;              // x-row half (64 rows)
        const int nw = (wid >> 1) * 64;      // W-row slice
        const int r8 = lane >> 2;
        const int cc = lane & 3;
        uint32_t swz[8];
        #pragma unroll
        for (int u = 0; u < 8; u++) swz[u] = (uint32_t)((u ^ r8) << 4);
        const uint32_t pbW = (uint32_t)((nw + r8) * 128 + cc * 4);

        int cs = 0, cph = 0;
        for (int c = 0; c < NK; c++) {
            MBARRIER_WAIT_PARITY(sb + OFF_FULL + cs * 8, cph);

            const uint32_t stg = sb + SMEM_HDR + (uint32_t)cs * STAGE_BYTES;
            const uint32_t wb  = stg + pbW;
            const uint32_t xbs = stg + W_STAGE + (uint32_t)(wm * 4 * 2048) + (uint32_t)(lane * 16);

            #pragma unroll
            for (int s = 0; s < 4; s++) {
                const uint32_t off0 = swz[2 * s], off1 = swz[2 * s + 1];

                // W (B-operand) fragments: 16 LDS.32, conflict-free
                float fb0[8], fb1[8];
                #pragma unroll
                for (int j = 0; j < 8; j++) {
                    fb0[j] = ldsf(wb + (uint32_t)(j * 1024) + off0);
                    fb1[j] = ldsf(wb + (uint32_t)(j * 1024) + off1);
                }
                uint32_t ub0[8], ub1[8];
                #pragma unroll
                for (int j = 0; j < 8; j++) { ub0[j] = f2tf(fb0[j]); ub1[j] = f2tf(fb1[j]); }

                // x (A-operand): one LDS.128 per m16-block, pre-rounded tf32
                #pragma unroll
                for (int i = 0; i < 4; i++) {
                    uint32_t a0, a1, a2, a3;
                    lds128(xbs + (uint32_t)((i * 4 + s) * 512), a0, a1, a2, a3);
                    #pragma unroll
                    for (int j = 0; j < 8; j++)
                        mma_tf32(acc[i][j], a0, a1, a2, a3, ub0[j], ub1[j]);
                }
            }

            if (lane == 0) MBARRIER_ARRIVE(sb + OFF_EMPTY + cs * 8);
            if (++cs == STAGES) { cs = 0; cph ^= 1; }
        }

        // ---------------- epilogue: partial -> its buffer ----------------
        float* ob;
        int stride;
        if (isA) { ob = g_Y2[kq]; stride = 512; }
        else     { ob = kq ? g_P[kq - 1] : d_out; stride = 8192; }
        #pragma unroll
        for (int i = 0; i < 4; i++) {
            #pragma unroll
            for (int j = 0; j < 8; j++) {
                int m = wm * 64 + 16 * i + r8;
                int n = row0 + nw + 8 * j + 2 * cc;
                *reinterpret_cast<float2*>(&ob[(size_t)m * stride + n]) =
                    make_float2(acc[i][j][0], acc[i][j][1]);
                *reinterpret_cast<float2*>(&ob[(size_t)(m + 8) * stride + n]) =
                    make_float2(acc[i][j][2], acc[i][j][3]);
            }
        }
    }
}

// ---------------- combine kernel ----------------
// out[m,16q+e] = out + P1 + P2 + P3 + 2*s*B[e]*sum_kq Y2[kq][m,q]
__global__ void __launch_bounds__(256)
lokr_combine(const float* __restrict__ lokrB, const float* __restrict__ scalar,
             float* __restrict__ out)
{
    int g = blockIdx.x * blockDim.x + threadIdx.x;   // 0..65535
    int m = g >> 9;
    int q = g & 511;
    int yi = m * 512 + q;
    float coef = 2.0f * scalar[0] *
        (g_Y2[0][yi] + g_Y2[1][yi] + g_Y2[2][yi] + g_Y2[3][yi]);

    const float4* Bv = reinterpret_cast<const float4*>(lokrB);
    size_t base = ((size_t)m * 8192 + (size_t)q * 16) >> 2;
    float4* o4 = reinterpret_cast<float4*>(out);
    const float4* p1 = reinterpret_cast<const float4*>(g_P[0]);
    const float4* p2 = reinterpret_cast<const float4*>(g_P[1]);
    const float4* p3 = reinterpret_cast<const float4*>(g_P[2]);

    #pragma unroll
    for (int t = 0; t < 4; t++) {
        float4 o = o4[base + t];
        float4 a = p1[base + t];
        float4 bb = p2[base + t];
        float4 cC = p3[base + t];
        float4 bv = Bv[t];
        o.x += a.x + bb.x + cC.x + coef * bv.x;
        o.y += a.y + bb.y + cC.y + coef * bv.y;
        o.z += a.z + bb.z + cC.z + coef * bv.z;
        o.w += a.w + bb.w + cC.w + coef * bv.w;
        o4[base + t] = o;
    }
}

// ---------------- host ----------------
typedef CUresult (*EncodeFn)(CUtensorMap*, CUtensorMapDataType, cuuint32_t, void*,
                             const cuuint64_t*, const cuuint64_t*, const cuuint32_t*,
                             const cuuint32_t*, CUtensorMapInterleave, CUtensorMapSwizzle,
                             CUtensorMapL2promotion, CUtensorMapFloatOOBfill);

static void make_map2d(EncodeFn enc, CUtensorMap* m, const float* base, uint64_t rows) {
    cuuint64_t dims[2]    = { 8192ull, rows };
    cuuint64_t strides[1] = { 8192ull * sizeof(float) };
    cuuint32_t box[2]     = { 32u, 256u };   // 128B-wide box (SW128 atom), 256 rows
    cuuint32_t es[2]      = { 1u, 1u };
    enc(m, CU_TENSOR_MAP_DATA_TYPE_FLOAT32, 2, (void*)base,
        dims, strides, box, es,
        CU_TENSOR_MAP_INTERLEAVE_NONE, CU_TENSOR_MAP_SWIZZLE_128B,
        CU_TENSOR_MAP_L2_PROMOTION_L2_128B, CU_TENSOR_MAP_FLOAT_OOB_FILL_NONE);
}

extern "C" void kernel_launch(void* const* d_in, const int* in_sizes, int n_in,
                              void* d_out, int out_size)
{
    (void)in_sizes; (void)n_in; (void)out_size;
    const float* x  = (const float*)d_in[0];
    const float* W  = (const float*)d_in[1];
    const float* A  = (const float*)d_in[2];
    const float* B  = (const float*)d_in[3];
    const float* sc = (const float*)d_in[4];

    void* fn = nullptr;
    cudaDriverEntryPointQueryResult qr;
    cudaGetDriverEntryPointByVersion("cuTensorMapEncodeTiled", &fn, 12000,
                                     cudaEnableDefault, &qr);
    EncodeFn enc = (EncodeFn)fn;

    CUtensorMap wm, am;
    make_map2d(enc, &wm, W, 8192);
    make_map2d(enc, &am, A, 512);

    cudaFuncSetAttribute(lokr_gemm, cudaFuncAttributeMaxDynamicSharedMemorySize, SMEM_BYTES);

    prep_x<<<1024, 256>>>(x);
    lokr_gemm<<<136, 288, SMEM_BYTES>>>(wm, am, (float*)d_out);
    lokr_combine<<<256, 256>>>(B, sc, (float*)d_out);
}